// round 15
// baseline (speedup 1.0000x reference)
#include <cuda_runtime.h>
#include <cuda_bf16.h>
#include <math.h>
#include <stdint.h>

#define NCONF 8192
#define NT 64
#define NX 64
#define GRIDC 888   // 148 SMs * 6 CTAs

// Fused rolled-W fragment table: [T0][kk][nt][lane] -> uint4(hi0, hi1, lo0, lo1)
__device__ uint4 BV[64 * 4 * 8 * 32];   // 1 MB (L2-resident)

// -------- dynamic smem layout (bytes) --------
// AH [64][128B] at 0 (8192), AL at 8192 (8192)
// stage overlay [0,17408) = float[4][16][68]
// sB uint4[1024] at 17408 (16384) -- disjoint from stage
#define SM_AH     0
#define SM_AL     8192
#define SM_B      17408
#define SM_TOTAL  33792

static __device__ __forceinline__ uint32_t smem_u32(const void* p) {
    uint32_t a;
    asm("{ .reg .u64 t; cvta.to.shared.u64 t, %1; cvt.u32.u64 %0, t; }" : "=r"(a) : "l"(p));
    return a;
}
static __device__ __forceinline__ uint32_t pack_hi2(float x, float y) {
    uint32_t r;
    asm("cvt.rn.bf16x2.f32 %0, %1, %2;" : "=r"(r) : "f"(y), "f"(x)); // lo16=bf16(x)
    return r;
}
static __device__ __forceinline__ void cvt_split(float x, float y,
                                                 uint32_t& hi, uint32_t& lo) {
    uint32_t h = pack_hi2(x, y);
    float hx = __uint_as_float(h << 16);
    float hy = __uint_as_float(h & 0xffff0000u);
    lo = pack_hi2(x - hx, y - hy);
    hi = h;
}
static __device__ __forceinline__ void ldsm_x4(uint32_t& r0, uint32_t& r1,
                                               uint32_t& r2, uint32_t& r3, uint32_t addr) {
    asm volatile("ldmatrix.sync.aligned.m8n8.x4.shared.b16 {%0,%1,%2,%3}, [%4];"
                 : "=r"(r0), "=r"(r1), "=r"(r2), "=r"(r3) : "r"(addr));
}
static __device__ __forceinline__ void mma_bf16(float* d, uint32_t a0, uint32_t a1,
                                                uint32_t a2, uint32_t a3,
                                                uint32_t b0, uint32_t b1) {
    asm volatile(
        "mma.sync.aligned.m16n8k16.row.col.f32.bf16.bf16.f32 "
        "{%0,%1,%2,%3}, {%4,%5,%6,%7}, {%8,%9}, {%0,%1,%2,%3};"
        : "+f"(d[0]), "+f"(d[1]), "+f"(d[2]), "+f"(d[3])
        : "r"(a0), "r"(a1), "r"(a2), "r"(a3), "r"(b0), "r"(b1));
}
static __device__ __forceinline__ int t0_reduce(float2 v0, float2 v1, int lane) {
    float b0 = fabsf(v0.x); int j0 = lane;
    float c0 = fabsf(v1.x);
    if (c0 < b0) { b0 = c0; j0 = lane + 32; }
    float b1 = fabsf(v0.y); int j1 = lane;
    float c1 = fabsf(v1.y);
    if (c1 < b1) { b1 = c1; j1 = lane + 32; }
    #pragma unroll
    for (int off = 16; off > 0; off >>= 1) {
        float ob = __shfl_xor_sync(0xffffffffu, b0, off);
        int   oj = __shfl_xor_sync(0xffffffffu, j0, off);
        if (ob < b0 || (ob == b0 && oj < j0)) { b0 = ob; j0 = oj; }
        ob = __shfl_xor_sync(0xffffffffu, b1, off);
        oj = __shfl_xor_sync(0xffffffffu, j1, off);
        if (ob < b1 || (ob == b1 && oj < j1)) { b1 = ob; j1 = oj; }
    }
    return (j0 > j1) ? j1 : j0;
}
static __device__ __forceinline__ void b_issue(uint32_t sbase, int T0, int tid) {
    uint32_t dstBase = sbase + SM_B;
    const uint4* src = BV + T0 * 1024 + tid;
    #pragma unroll
    for (int k2 = 0; k2 < 8; ++k2) {
        uint32_t dst = dstBase + (uint32_t)(tid + k2 * 128) * 16;
        asm volatile("cp.async.cg.shared.global [%0], [%1], 16;"
                     :: "r"(dst), "l"(__cvta_generic_to_global(src + k2 * 128)));
    }
    asm volatile("cp.async.commit_group;" ::: "memory");
}
// convert + store pre-loaded raw A rows (warp-private rows 16*wid..+15)
static __device__ __forceinline__ void a_store(char* smem, const float4* v,
                                               int wid, int lane) {
    #pragma unroll
    for (int s = 0; s < 8; ++s) {
        int idx = wid * 256 + 32 * s + lane;
        int mrow = idx >> 4;
        int q    = idx & 15;
        uint32_t off = (uint32_t)mrow * 128 +
                       ((uint32_t)((q >> 1) ^ (mrow & 7)) << 4) + ((q & 1) << 3);
        uint32_t hx, lx, hy, ly;
        cvt_split(v[s].x, v[s].y, hx, lx);
        cvt_split(v[s].z, v[s].w, hy, ly);
        *reinterpret_cast<uint2*>(smem + SM_AH + off) = make_uint2(hx, hy);
        *reinterpret_cast<uint2*>(smem + SM_AL + off) = make_uint2(lx, ly);
    }
}

// ---------------------------------------------------------------------------
__global__ void __launch_bounds__(64) prep_kernel(const float* __restrict__ W) {
    int T0 = blockIdx.x;
    for (int idx = threadIdx.x; idx < 1024; idx += 64) {
        int lane = idx & 31;
        int nt   = (idx >> 5) & 7;
        int kk   = idx >> 8;
        int n    = 8 * nt + (lane >> 2);
        int k0   = 16 * kk + (lane & 3) * 2;
        float w00 = W[(((k0     + T0) & 63) << 6) + n];
        float w01 = W[(((k0 + 1 + T0) & 63) << 6) + n];
        float w10 = W[(((k0 + 8 + T0) & 63) << 6) + n];
        float w11 = W[(((k0 + 9 + T0) & 63) << 6) + n];
        uint32_t h0, l0, h1, l1;
        cvt_split(w00, w01, h0, l0);
        cvt_split(w10, w11, h1, l1);
        BV[T0 * 1024 + idx] = make_uint4(h0, h1, l0, l1);
    }
}

// ---------------------------------------------------------------------------
// Main: persistent. Block 0: LU(W) + logDet tail. Blocks 1..888: configs
// i = blk-1, blk-1+888, ...  Warp w: rows 16w..16w+15 of each config.
// Next-config raw A is register-prefetched during the epilogue.
// ---------------------------------------------------------------------------
__global__ void __launch_bounds__(128, 6) main_kernel(
    const float* __restrict__ phi, const float* __restrict__ W,
    const float* __restrict__ b, float* __restrict__ out, int write_logdet)
{
    extern __shared__ char smem[];
    uint32_t sbase = smem_u32(smem);
    int tid  = threadIdx.x;
    int wid  = tid >> 5;
    int lane = tid & 31;

    if (blockIdx.x == 0) {   // ---------------- LU block ----------------
        float (*A)[65] = reinterpret_cast<float(*)[65]>(smem);
        float* m   = reinterpret_cast<float*>(smem + 16640);
        float* rv  = reinterpret_cast<float*>(smem + 16896);
        int*   ri  = reinterpret_cast<int*>(smem + 16904);
        float* sld = reinterpret_cast<float*>(smem + 16912);

        for (int idx = tid; idx < 64 * 64; idx += 128)
            A[idx >> 6][idx & 63] = W[idx];
        __syncthreads();

        float ld = 0.0f;
        for (int k = 0; k < 64; ++k) {
            if (tid < 64) {
                float v  = (tid >= k) ? fabsf(A[tid][k]) : -1.0f;
                int   vi = tid;
                #pragma unroll
                for (int off = 16; off > 0; off >>= 1) {
                    float ov = __shfl_down_sync(0xffffffffu, v,  off);
                    int   oi = __shfl_down_sync(0xffffffffu, vi, off);
                    if (ov > v) { v = ov; vi = oi; }
                }
                if ((tid & 31) == 0) { rv[tid >> 5] = v; ri[tid >> 5] = vi; }
            }
            __syncthreads();
            int p = (rv[1] > rv[0]) ? ri[1] : ri[0];
            if (tid < 64 && p != k) {
                float t1 = A[k][tid], t2 = A[p][tid];
                A[k][tid] = t2; A[p][tid] = t1;
            }
            __syncthreads();
            float piv = A[k][k];
            if (tid < 64) {
                ld += logf(fabsf(piv));
                if (tid > k) m[tid] = A[tid][k] / piv;
            }
            __syncthreads();
            if (tid < 64 && tid > k) {
                float akj = A[k][tid];
                for (int r = k + 1; r < 64; ++r)
                    A[r][tid] -= m[r] * akj;
            }
            __syncthreads();
        }
        if (write_logdet) {
            if (tid == 0) *sld = ld;
            __syncthreads();
            float val = (float)NT * (*sld);
            float* tail = out + (size_t)NCONF * NT * NX;
            for (int idx = tid; idx < NCONF; idx += 128)
                tail[idx] = val;
        }
        return;
    }

    int i = blockIdx.x - 1;                         // first config
    const float* phic = phi + (size_t)i * (NT * NX);

    // --- prologue for first config ---
    int T0;
    {
        float2 u0 = *reinterpret_cast<const float2*>(phic + (size_t)lane * NX);
        float2 u1 = *reinterpret_cast<const float2*>(phic + (size_t)(lane + 32) * NX);
        T0 = t0_reduce(u0, u1, lane);
    }
    b_issue(sbase, T0, tid);
    {
        float4 v[8];
        const float4* g4 = reinterpret_cast<const float4*>(phic);
        #pragma unroll
        for (int s = 0; s < 8; ++s) v[s] = g4[wid * 256 + 32 * s + lane];
        a_store(smem, v, wid, lane);
    }
    __syncwarp();
    asm volatile("cp.async.wait_group 0;" ::: "memory");
    __syncthreads();

    int mrel = (lane & 7) + ((lane >> 3) & 1) * 8;
    int csel = (lane >> 4) & 1;
    int mm   = 16 * wid + mrel;
    int qrow = lane >> 2;
    int qcol = (lane & 3) * 2;

    for (;;) {
        int offs = (64 - T0) & 63;

        // --- MMA loop ---
        const uint4* bBase = reinterpret_cast<const uint4*>(smem + SM_B) + lane;
        float d[8][4];
        #pragma unroll
        for (int nt = 0; nt < 8; ++nt)
            #pragma unroll
            for (int e = 0; e < 4; ++e) d[nt][e] = 0.0f;

        #pragma unroll
        for (int kk = 0; kk < 4; ++kk) {
            uint32_t co = (uint32_t)((kk * 2 + csel) ^ (mm & 7)) << 4;
            uint32_t rowoff = (uint32_t)mm * 128 + co;
            uint32_t ahi[4], alo[4];
            ldsm_x4(ahi[0], ahi[1], ahi[2], ahi[3], sbase + SM_AH + rowoff);
            ldsm_x4(alo[0], alo[1], alo[2], alo[3], sbase + SM_AL + rowoff);
            const uint4* bk = bBase + kk * 256;
            #pragma unroll
            for (int nt = 0; nt < 8; ++nt) {
                uint4 w = bk[nt * 32];
                mma_bf16(d[nt], ahi[0], ahi[1], ahi[2], ahi[3], w.x, w.y);
                mma_bf16(d[nt], alo[0], alo[1], alo[2], alo[3], w.x, w.y);
                mma_bf16(d[nt], ahi[0], ahi[1], ahi[2], ahi[3], w.z, w.w);
            }
        }
        __syncthreads();   // (1) all warps done with A (stage overlays A) & B

        int inext = i + GRIDC;
        bool more = (inext < NCONF);
        const float* phin = phi + (size_t)inext * (NT * NX);

        // --- epilogue: +bias, roll into stage; accumulators die here ---
        float* st = reinterpret_cast<float*>(smem) + wid * (16 * 68);
        #pragma unroll
        for (int nt = 0; nt < 8; ++nt) {
            int jb = 8 * nt + qcol;
            float2 bias = __ldg(reinterpret_cast<const float2*>(b + jb));
            int j0 = (jb + offs) & 63;
            int j1 = (jb + 1 + offs) & 63;
            st[qrow * 68 + j0]       = d[nt][0] + bias.x;
            st[qrow * 68 + j1]       = d[nt][1] + bias.y;
            st[(qrow + 8) * 68 + j0] = d[nt][2] + bias.x;
            st[(qrow + 8) * 68 + j1] = d[nt][3] + bias.y;
        }

        // --- register-prefetch next config: raw A (reuses dead d regs) + T0 ---
        float4 v[8];
        float2 w0, w1;
        if (more) {
            const float4* g4n = reinterpret_cast<const float4*>(phin);
            #pragma unroll
            for (int s = 0; s < 8; ++s) v[s] = g4n[wid * 256 + 32 * s + lane];
            w0 = *reinterpret_cast<const float2*>(phin + (size_t)lane * NX);
            w1 = *reinterpret_cast<const float2*>(phin + (size_t)(lane + 32) * NX);
        }
        __syncwarp();

        // --- flush: coalesced float4 rows (covers A-load latency) ---
        float* obase = out + (size_t)i * (NT * NX) + (size_t)(16 * wid) * NX;
        #pragma unroll
        for (int it = 0; it < 8; ++it) {
            int r  = it * 2 + (lane >> 4);
            int c4 = (lane & 15) * 4;
            float4 vv = *reinterpret_cast<const float4*>(st + r * 68 + c4);
            *reinterpret_cast<float4*>(obase + (size_t)r * NX + c4) = vv;
        }

        if (!more) break;

        // next-config B prefetch (B region disjoint; safe after bar (1))
        T0 = t0_reduce(w0, w1, lane);
        b_issue(sbase, T0, tid);
        __syncthreads();   // (2) all flushes done -> A/stage region writable

        // convert prefetched A (loads long in flight) and store to smem
        a_store(smem, v, wid, lane);

        i = inext;
        __syncwarp();
        asm volatile("cp.async.wait_group 0;" ::: "memory");
        __syncthreads();   // (3) B visible
    }
}

// ---------------------------------------------------------------------------
extern "C" void kernel_launch(void* const* d_in, const int* in_sizes, int n_in,
                              void* d_out, int out_size) {
    const float* phi = nullptr;
    const float* W   = nullptr;
    const float* b   = nullptr;
    for (int k = 0; k < n_in; ++k) {
        if      (in_sizes[k] == NCONF * NT * NX) phi = (const float*)d_in[k];
        else if (in_sizes[k] == NX * NX)         W   = (const float*)d_in[k];
        else if (in_sizes[k] == NX)              b   = (const float*)d_in[k];
    }
    float* out = (float*)d_out;
    int write_logdet = (out_size >= NCONF * NT * NX + NCONF) ? 1 : 0;

    cudaFuncSetAttribute(main_kernel, cudaFuncAttributeMaxDynamicSharedMemorySize, SM_TOTAL);
    prep_kernel<<<64, 64>>>(W);
    main_kernel<<<GRIDC + 1, 128, SM_TOTAL>>>(phi, W, b, out, write_logdet);
}

// round 16
// speedup vs baseline: 1.0572x; 1.0572x over previous
#include <cuda_runtime.h>
#include <cuda_bf16.h>
#include <math.h>
#include <stdint.h>

#define NCONF 8192
#define NT 64
#define NX 64
#define GRIDC 888   // 148 SMs * 6 CTAs

// -------- dynamic smem layout (bytes) --------
// AH [64 rows][128B bf16] at 0      (8192)
// AL                      at 8192   (8192)
// BH [64 rows][128B bf16] at 16384  (8192)   W unrolled, hi   (constant per CTA)
// BL                      at 24576  (8192)   W unrolled, lo
// stage overlay [0, 8704) = float[4 warps][8 rows][68]
#define SM_AH     0
#define SM_AL     8192
#define SM_BH     16384
#define SM_BL     24576
#define SM_TOTAL  32768

static __device__ __forceinline__ uint32_t smem_u32(const void* p) {
    uint32_t a;
    asm("{ .reg .u64 t; cvta.to.shared.u64 t, %1; cvt.u32.u64 %0, t; }" : "=r"(a) : "l"(p));
    return a;
}
static __device__ __forceinline__ uint32_t pack_hi2(float x, float y) {
    uint32_t r;
    asm("cvt.rn.bf16x2.f32 %0, %1, %2;" : "=r"(r) : "f"(y), "f"(x)); // lo16=bf16(x)
    return r;
}
static __device__ __forceinline__ void cvt_split(float x, float y,
                                                 uint32_t& hi, uint32_t& lo) {
    uint32_t h = pack_hi2(x, y);
    float hx = __uint_as_float(h << 16);
    float hy = __uint_as_float(h & 0xffff0000u);
    lo = pack_hi2(x - hx, y - hy);
    hi = h;
}
static __device__ __forceinline__ void ldsm_x4(uint32_t& r0, uint32_t& r1,
                                               uint32_t& r2, uint32_t& r3, uint32_t addr) {
    asm volatile("ldmatrix.sync.aligned.m8n8.x4.shared.b16 {%0,%1,%2,%3}, [%4];"
                 : "=r"(r0), "=r"(r1), "=r"(r2), "=r"(r3) : "r"(addr));
}
static __device__ __forceinline__ void ldsm_x4t(uint32_t& r0, uint32_t& r1,
                                                uint32_t& r2, uint32_t& r3, uint32_t addr) {
    asm volatile("ldmatrix.sync.aligned.m8n8.x4.trans.shared.b16 {%0,%1,%2,%3}, [%4];"
                 : "=r"(r0), "=r"(r1), "=r"(r2), "=r"(r3) : "r"(addr));
}
static __device__ __forceinline__ void mma_bf16(float* d, uint32_t a0, uint32_t a1,
                                                uint32_t a2, uint32_t a3,
                                                uint32_t b0, uint32_t b1) {
    asm volatile(
        "mma.sync.aligned.m16n8k16.row.col.f32.bf16.bf16.f32 "
        "{%0,%1,%2,%3}, {%4,%5,%6,%7}, {%8,%9}, {%0,%1,%2,%3};"
        : "+f"(d[0]), "+f"(d[1]), "+f"(d[2]), "+f"(d[3])
        : "r"(a0), "r"(a1), "r"(a2), "r"(a3), "r"(b0), "r"(b1));
}
static __device__ __forceinline__ int t0_reduce(float2 v0, float2 v1, int lane) {
    float b0 = fabsf(v0.x); int j0 = lane;
    float c0 = fabsf(v1.x);
    if (c0 < b0) { b0 = c0; j0 = lane + 32; }
    float b1 = fabsf(v0.y); int j1 = lane;
    float c1 = fabsf(v1.y);
    if (c1 < b1) { b1 = c1; j1 = lane + 32; }
    #pragma unroll
    for (int off = 16; off > 0; off >>= 1) {
        float ob = __shfl_xor_sync(0xffffffffu, b0, off);
        int   oj = __shfl_xor_sync(0xffffffffu, j0, off);
        if (ob < b0 || (ob == b0 && oj < j0)) { b0 = ob; j0 = oj; }
        ob = __shfl_xor_sync(0xffffffffu, b1, off);
        oj = __shfl_xor_sync(0xffffffffu, j1, off);
        if (ob < b1 || (ob == b1 && oj < j1)) { b1 = ob; j1 = oj; }
    }
    return (j0 > j1) ? j1 : j0;
}
// stage A for this config: warp-private rows 16*wid..+15, gmem -> bf16 hi/lo
static __device__ __forceinline__ void a_stage(char* smem, const float* phic,
                                               int wid, int lane) {
    const float4* g4 = reinterpret_cast<const float4*>(phic);
    #pragma unroll
    for (int s = 0; s < 8; ++s) {
        int idx = wid * 256 + 32 * s + lane;
        float4 v = g4[idx];
        int mrow = idx >> 4;
        int q    = idx & 15;
        uint32_t off = (uint32_t)mrow * 128 +
                       ((uint32_t)((q >> 1) ^ (mrow & 7)) << 4) + ((q & 1) << 3);
        uint32_t hx, lx, hy, ly;
        cvt_split(v.x, v.y, hx, lx);
        cvt_split(v.z, v.w, hy, ly);
        *reinterpret_cast<uint2*>(smem + SM_AH + off) = make_uint2(hx, hy);
        *reinterpret_cast<uint2*>(smem + SM_AL + off) = make_uint2(lx, ly);
    }
}

// ---------------------------------------------------------------------------
// Persistent kernel. Block 0: LU(W) + logDet tail. Blocks 1..GRIDC: configs
// i = blk-1, blk-1+GRIDC, ...  Warp w owns rows 16w..16w+15.
// B = W (unrolled) in smem once per CTA; T0-roll lives in the per-lane
// ldmatrix.trans row addresses (verified in R5).
// ---------------------------------------------------------------------------
__global__ void __launch_bounds__(128, 6) main_kernel(
    const float* __restrict__ phi, const float* __restrict__ W,
    const float* __restrict__ b, float* __restrict__ out, int write_logdet)
{
    extern __shared__ char smem[];
    uint32_t sbase = smem_u32(smem);
    int tid  = threadIdx.x;
    int wid  = tid >> 5;
    int lane = tid & 31;

    if (blockIdx.x == 0) {   // ---------------- LU block ----------------
        float (*A)[65] = reinterpret_cast<float(*)[65]>(smem);
        float* m   = reinterpret_cast<float*>(smem + 16640);
        float* rv  = reinterpret_cast<float*>(smem + 16896);
        int*   ri  = reinterpret_cast<int*>(smem + 16904);
        float* sld = reinterpret_cast<float*>(smem + 16912);

        for (int idx = tid; idx < 64 * 64; idx += 128)
            A[idx >> 6][idx & 63] = W[idx];
        __syncthreads();

        float ld = 0.0f;
        for (int k = 0; k < 64; ++k) {
            if (tid < 64) {
                float v  = (tid >= k) ? fabsf(A[tid][k]) : -1.0f;
                int   vi = tid;
                #pragma unroll
                for (int off = 16; off > 0; off >>= 1) {
                    float ov = __shfl_down_sync(0xffffffffu, v,  off);
                    int   oi = __shfl_down_sync(0xffffffffu, vi, off);
                    if (ov > v) { v = ov; vi = oi; }
                }
                if ((tid & 31) == 0) { rv[tid >> 5] = v; ri[tid >> 5] = vi; }
            }
            __syncthreads();
            int p = (rv[1] > rv[0]) ? ri[1] : ri[0];
            if (tid < 64 && p != k) {
                float t1 = A[k][tid], t2 = A[p][tid];
                A[k][tid] = t2; A[p][tid] = t1;
            }
            __syncthreads();
            float piv = A[k][k];
            if (tid < 64) {
                ld += logf(fabsf(piv));
                if (tid > k) m[tid] = A[tid][k] / piv;
            }
            __syncthreads();
            if (tid < 64 && tid > k) {
                float akj = A[k][tid];
                for (int r = k + 1; r < 64; ++r)
                    A[r][tid] -= m[r] * akj;
            }
            __syncthreads();
        }
        if (write_logdet) {
            if (tid == 0) *sld = ld;
            __syncthreads();
            float val = (float)NT * (*sld);
            float* tail = out + (size_t)NCONF * NT * NX;
            for (int idx = tid; idx < NCONF; idx += 128)
                tail[idx] = val;
        }
        return;
    }

    int i = blockIdx.x - 1;
    const float* phic = phi + (size_t)i * (NT * NX);

    // --- one-time B: W -> bf16 hi/lo, straight layout + swizzle ---
    {
        const float4* w4 = reinterpret_cast<const float4*>(W);
        #pragma unroll
        for (int s = 0; s < 8; ++s) {
            int idx = tid + 128 * s;            // 0..1023 float4s
            float4 v = w4[idx];
            int vrow = idx >> 4;
            int q    = idx & 15;
            uint32_t off = (uint32_t)vrow * 128 +
                           ((uint32_t)((q >> 1) ^ (vrow & 7)) << 4) + ((q & 1) << 3);
            uint32_t hx, lx, hy, ly;
            cvt_split(v.x, v.y, hx, lx);
            cvt_split(v.z, v.w, hy, ly);
            *reinterpret_cast<uint2*>(smem + SM_BH + off) = make_uint2(hx, hy);
            *reinterpret_cast<uint2*>(smem + SM_BL + off) = make_uint2(lx, ly);
        }
    }

    // --- first-config prologue ---
    int T0;
    {
        float2 u0 = *reinterpret_cast<const float2*>(phic + (size_t)lane * NX);
        float2 u1 = *reinterpret_cast<const float2*>(phic + (size_t)(lane + 32) * NX);
        T0 = t0_reduce(u0, u1, lane);
    }
    a_stage(smem, phic, wid, lane);
    __syncthreads();

    int mrel = (lane & 7) + ((lane >> 3) & 1) * 8;
    int csel = (lane >> 4) & 1;
    int mm   = 16 * wid + mrel;
    int qrow = lane >> 2;
    int qcol = (lane & 3) * 2;

    for (;;) {
        int offs = (64 - T0) & 63;

        // --- MMA loop: A own rows; B rolled via per-lane trans row address ---
        float d[8][4];
        #pragma unroll
        for (int nt = 0; nt < 8; ++nt)
            #pragma unroll
            for (int e = 0; e < 4; ++e) d[nt][e] = 0.0f;

        #pragma unroll
        for (int kk = 0; kk < 4; ++kk) {
            uint32_t co = (uint32_t)((kk * 2 + csel) ^ (mm & 7)) << 4;
            uint32_t rowoff = (uint32_t)mm * 128 + co;
            uint32_t ahi[4], alo[4];
            ldsm_x4(ahi[0], ahi[1], ahi[2], ahi[3], sbase + SM_AH + rowoff);
            ldsm_x4(alo[0], alo[1], alo[2], alo[3], sbase + SM_AL + rowoff);

            int vphys = (kk * 16 + mrel + T0) & 63;   // rolled W row
            uint32_t bro = (uint32_t)vphys * 128;
            int vb = vphys & 7;

            #pragma unroll
            for (int np = 0; np < 4; ++np) {
                uint32_t bc = (uint32_t)((np * 2 + csel) ^ vb) << 4;
                uint32_t b0, b1, b2, b3;
                ldsm_x4t(b0, b1, b2, b3, sbase + SM_BH + bro + bc);
                mma_bf16(d[2 * np],     ahi[0], ahi[1], ahi[2], ahi[3], b0, b1);
                mma_bf16(d[2 * np + 1], ahi[0], ahi[1], ahi[2], ahi[3], b2, b3);
                mma_bf16(d[2 * np],     alo[0], alo[1], alo[2], alo[3], b0, b1);
                mma_bf16(d[2 * np + 1], alo[0], alo[1], alo[2], alo[3], b2, b3);
            }
            #pragma unroll
            for (int np = 0; np < 4; ++np) {
                uint32_t bc = (uint32_t)((np * 2 + csel) ^ vb) << 4;
                uint32_t b0, b1, b2, b3;
                ldsm_x4t(b0, b1, b2, b3, sbase + SM_BL + bro + bc);
                mma_bf16(d[2 * np],     ahi[0], ahi[1], ahi[2], ahi[3], b0, b1);
                mma_bf16(d[2 * np + 1], ahi[0], ahi[1], ahi[2], ahi[3], b2, b3);
            }
        }
        __syncthreads();   // (1) all warps done reading A (stage overlays A)

        int inext = i + GRIDC;
        bool more = (inext < NCONF);
        const float* phin = phi + (size_t)inext * (NT * NX);

        // --- two-phase epilogue: stage 8 rows (stride 68), flush, repeat ---
        float* st = reinterpret_cast<float*>(smem) + wid * (8 * 68);
        float* obase = out + (size_t)i * (NT * NX) + (size_t)(16 * wid) * NX;

        // phase 1: rows qrow (d[.][0], d[.][1])
        #pragma unroll
        for (int nt = 0; nt < 8; ++nt) {
            int jb = 8 * nt + qcol;
            float2 bias = __ldg(reinterpret_cast<const float2*>(b + jb));
            st[qrow * 68 + ((jb + offs) & 63)]     = d[nt][0] + bias.x;
            st[qrow * 68 + ((jb + 1 + offs) & 63)] = d[nt][1] + bias.y;
        }
        // next-config T0 loads issued early (covered by flush)
        float2 w0, w1;
        if (more) {
            w0 = *reinterpret_cast<const float2*>(phin + (size_t)lane * NX);
            w1 = *reinterpret_cast<const float2*>(phin + (size_t)(lane + 32) * NX);
        }
        __syncwarp();
        #pragma unroll
        for (int it = 0; it < 4; ++it) {
            int r  = it * 2 + (lane >> 4);      // 0..7
            int c4 = (lane & 15) * 4;
            float4 v = *reinterpret_cast<const float4*>(st + r * 68 + c4);
            *reinterpret_cast<float4*>(obase + (size_t)r * NX + c4) = v;
        }
        __syncwarp();
        // phase 2: rows qrow+8 (d[.][2], d[.][3])
        #pragma unroll
        for (int nt = 0; nt < 8; ++nt) {
            int jb = 8 * nt + qcol;
            float2 bias = __ldg(reinterpret_cast<const float2*>(b + jb));
            st[qrow * 68 + ((jb + offs) & 63)]     = d[nt][2] + bias.x;
            st[qrow * 68 + ((jb + 1 + offs) & 63)] = d[nt][3] + bias.y;
        }
        __syncwarp();
        #pragma unroll
        for (int it = 0; it < 4; ++it) {
            int r  = it * 2 + (lane >> 4);
            int c4 = (lane & 15) * 4;
            float4 v = *reinterpret_cast<const float4*>(st + r * 68 + c4);
            *reinterpret_cast<float4*>(obase + (size_t)(r + 8) * NX + c4) = v;
        }

        if (!more) break;

        T0 = t0_reduce(w0, w1, lane);
        __syncthreads();   // (2) all flushes done -> A/stage region writable

        a_stage(smem, phin, wid, lane);   // warp-private rows; B untouched
        __syncwarp();
        i = inext;
    }
}

// ---------------------------------------------------------------------------
extern "C" void kernel_launch(void* const* d_in, const int* in_sizes, int n_in,
                              void* d_out, int out_size) {
    const float* phi = nullptr;
    const float* W   = nullptr;
    const float* b   = nullptr;
    for (int k = 0; k < n_in; ++k) {
        if      (in_sizes[k] == NCONF * NT * NX) phi = (const float*)d_in[k];
        else if (in_sizes[k] == NX * NX)         W   = (const float*)d_in[k];
        else if (in_sizes[k] == NX)              b   = (const float*)d_in[k];
    }
    float* out = (float*)d_out;
    int write_logdet = (out_size >= NCONF * NT * NX + NCONF) ? 1 : 0;

    cudaFuncSetAttribute(main_kernel, cudaFuncAttributeMaxDynamicSharedMemorySize, SM_TOTAL);
    main_kernel<<<GRIDC + 1, 128, SM_TOTAL>>>(phi, W, b, out, write_logdet);
}